// round 6
// baseline (speedup 1.0000x reference)
#include <cuda_runtime.h>

// x: [8,16,256,256] f32  ->  out: [8,64,256,256] f32
// Block 32x8, each thread computes 4 cols x 2 rows = 8 pixels. Tile 128x16.

#define TW 128
#define TH 16
#define SWU 130         // used smem cols (w-1 .. w+128)
#define SWA 132         // 16B-aligned rows
#define SH  18          // 16 rows + 2 halo
#define HW 65536

__device__ __forceinline__ float fsqrt_approx(float a) {
    float r; asm("sqrt.approx.f32 %0, %1;" : "=f"(r) : "f"(a)); return r;
}
__device__ __forceinline__ float frcp_approx(float a) {
    float r; asm("rcp.approx.f32 %0, %1;" : "=f"(r) : "f"(a)); return r;
}

__global__ __launch_bounds__(256, 4) void glcm_martingale_kernel(
    const float* __restrict__ x, float* __restrict__ out)
{
    __shared__ float xs[SH][SWA];
    __shared__ float ts[SH][SWA];

    const int img = blockIdx.z;                 // b*16+c
    const int h0  = blockIdx.y * TH;
    const int w0  = blockIdx.x * TW;
    const float* __restrict__ xin = x + (size_t)img * HW;

    // ---- cooperative tile load: rows h0-1..h0+16, cols w0-1..w0+128 ----
    const int tid = threadIdx.y * 32 + threadIdx.x;
    for (int idx = tid; idx < SH * SWU; idx += 256) {
        const int r = idx / SWU;
        const int c = idx - r * SWU;
        const int gh = h0 - 1 + r;
        const int gw = w0 - 1 + c;
        float v = 0.0f;
        if ((unsigned)gh < 256u && (unsigned)gw < 256u)
            v = xin[gh * 256 + gw];
        xs[r][c] = v;
        ts[r][c] = v * __logf(v + 1e-6f);   // 0*log(eps)=0 matches zero-pad
    }
    __syncthreads();

    const int ty = threadIdx.y, tx = threadIdx.x;
    const int cb = 4 * tx;       // smem col base (cols cb..cb+5)
    const int sr = 2 * ty;       // smem row base: rows sr..sr+3 feed 2 outputs

    // ---- load 4 rows of x values (kept for homogeneity) ----
    float v[4][6];
    #pragma unroll
    for (int r = 0; r < 4; r++) {
        const float4 a0 = *(const float4*)&xs[sr + r][cb];
        const float4 a1 = *(const float4*)&xs[sr + r][cb + 4];
        v[r][0] = a0.x; v[r][1] = a0.y; v[r][2] = a0.z;
        v[r][3] = a0.w; v[r][4] = a1.x; v[r][5] = a1.y;
    }

    // ---- middle-row (rows 1,2) shared partials ----
    float m1[6], m2[6], mt[6];
    {
        const float4 t1a = *(const float4*)&ts[sr + 1][cb];
        const float4 t1b = *(const float4*)&ts[sr + 1][cb + 4];
        const float4 t2a = *(const float4*)&ts[sr + 2][cb];
        const float4 t2b = *(const float4*)&ts[sr + 2][cb + 4];
        const float r1[6] = {t1a.x, t1a.y, t1a.z, t1a.w, t1b.x, t1b.y};
        const float r2[6] = {t2a.x, t2a.y, t2a.z, t2a.w, t2b.x, t2b.y};
        #pragma unroll
        for (int j = 0; j < 6; j++) {
            m1[j] = v[1][j] + v[2][j];
            m2[j] = fmaf(v[1][j], v[1][j], v[2][j] * v[2][j]);
            mt[j] = r1[j] + r2[j];
        }
    }

    const float inv9 = 1.0f / 9.0f;
    const float E  = 0.60653065971263342f;   // exp(-0.5)
    const float EE = 1e-6f * E;

    const int wbase = w0 + cb;
    float* __restrict__ obase = out + (size_t)img * 4 * HW + wbase;

    #pragma unroll
    for (int wr = 0; wr < 2; wr++) {
        const int e = wr ? 3 : 0;            // extra row index (top or bottom)

        // t for the extra row
        const float4 tea = *(const float4*)&ts[sr + e][cb];
        const float4 teb = *(const float4*)&ts[sr + e][cb + 4];
        const float te[6] = {tea.x, tea.y, tea.z, tea.w, teb.x, teb.y};

        float a1[6], a2[6], at[6];
        #pragma unroll
        for (int j = 0; j < 6; j++) {
            a1[j] = m1[j] + v[e][j];
            a2[j] = fmaf(v[e][j], v[e][j], m2[j]);
            at[j] = mt[j] + te[j];
        }

        float4 con, en, ent, ho;
        float* conp = &con.x; float* enp = &en.x;
        float* entp = &ent.x; float* hop = &ho.x;

        #pragma unroll
        for (int k = 0; k < 4; k++) {
            const float s1 = a1[k] + a1[k + 1] + a1[k + 2];
            const float s2 = a2[k] + a2[k + 1] + a2[k + 2];
            const float st = at[k] + at[k + 1] + at[k + 2];

            const float mean = s1 * inv9;
            float ss = fmaf(-s1, mean, s2);
            ss = fmaxf(ss, 0.0f);

            const float stdv = fsqrt_approx(ss * 0.125f) + 1e-6f;  // ddof=1
            const float rs = frcp_approx(stdv);
            const float contrast = ss * inv9 * rs * rs;

            // homogeneity: 3 partial trees for shorter dependency chain
            float sA = fabsf(v[wr    ][k    ] - mean)
                     + fabsf(v[wr    ][k + 1] - mean)
                     + fabsf(v[wr    ][k + 2] - mean);
            float sB = fabsf(v[wr + 1][k    ] - mean)
                     + fabsf(v[wr + 1][k + 1] - mean)
                     + fabsf(v[wr + 1][k + 2] - mean);
            float sC = fabsf(v[wr + 2][k    ] - mean)
                     + fabsf(v[wr + 2][k + 1] - mean)
                     + fabsf(v[wr + 2][k + 2] - mean);
            const float homog = frcp_approx(fmaf(sA + sB + sC, inv9, 1.0f));

            conp[k] = fmaf(contrast, E, EE);
            enp[k]  = fmaf(s2 * inv9, E, EE);
            entp[k] = fmaf(-st * inv9, E, EE);
            hop[k]  = fmaf(homog, E, EE);
        }

        const int h = h0 + 2 * ty + wr;
        float4* __restrict__ o = (float4*)(obase + h * 256);
        o[0 * HW / 4] = con;
        o[1 * HW / 4] = en;
        o[2 * HW / 4] = ent;
        o[3 * HW / 4] = ho;
    }
}

extern "C" void kernel_launch(void* const* d_in, const int* in_sizes, int n_in,
                              void* d_out, int out_size)
{
    const float* x = (const float*)d_in[0];
    float* out = (float*)d_out;
    (void)in_sizes; (void)n_in; (void)out_size;

    dim3 block(32, 8);
    dim3 grid(256 / TW, 256 / TH, 8 * 16);
    glcm_martingale_kernel<<<grid, block>>>(x, out);
}

// round 7
// speedup vs baseline: 1.6420x; 1.6420x over previous
#include <cuda_runtime.h>

// x: [8,16,256,256] f32 -> out: [8,64,256,256] f32
// No smem: each thread computes 4 horizontal pixels, loading its 3x6 window
// directly from global (L1-served overlaps). Block 32x8, grid (2,32,128).

#define HW 65536

__device__ __forceinline__ float fsqrt_approx(float a) {
    float r; asm("sqrt.approx.f32 %0, %1;" : "=f"(r) : "f"(a)); return r;
}
__device__ __forceinline__ float frcp_approx(float a) {
    float r; asm("rcp.approx.f32 %0, %1;" : "=f"(r) : "f"(a)); return r;
}

__global__ __launch_bounds__(256) void glcm_martingale_kernel(
    const float* __restrict__ x, float* __restrict__ out)
{
    const int img = blockIdx.z;                       // b*16+c
    const int h   = blockIdx.y * 8 + threadIdx.y;     // output row
    const int wb  = blockIdx.x * 128 + threadIdx.x * 4; // output col base (aligned)
    const float* __restrict__ xin = x + (size_t)img * HW;

    // ---- load 3x6 window: cols wb-1 .. wb+4 (j = global col - wb + 1) ----
    float v[3][6];
#pragma unroll
    for (int r = 0; r < 3; r++) {
        const int gh = h - 1 + r;
        float4 a = make_float4(0.f, 0.f, 0.f, 0.f);
        float vl = 0.f, vr = 0.f;
        if ((unsigned)gh < 256u) {
            const float* __restrict__ row = xin + gh * 256;
            a = *(const float4*)(row + wb);
            if (wb > 0)   vl = row[wb - 1];
            if (wb < 252) vr = row[wb + 4];   // wb+4 == 256 only when wb == 252
        }
        v[r][0] = vl;  v[r][1] = a.x; v[r][2] = a.y;
        v[r][3] = a.z; v[r][4] = a.w; v[r][5] = vr;
    }

    // ---- per-column sums over the 3 rows ----
    float c1[6], c2[6], ct[6];
#pragma unroll
    for (int j = 0; j < 6; j++) {
        const float v0 = v[0][j], v1 = v[1][j], v2 = v[2][j];
        c1[j] = v0 + v1 + v2;
        c2[j] = fmaf(v0, v0, fmaf(v1, v1, v2 * v2));
        ct[j] = v0 * __logf(v0 + 1e-6f)
              + v1 * __logf(v1 + 1e-6f)
              + v2 * __logf(v2 + 1e-6f);   // 0*log(eps) = 0 matches zero-pad
    }

    const float inv9 = 1.0f / 9.0f;

    // ---- per-pixel window sums ----
    float mean[4], ss[4], s2a[4], sta[4];
#pragma unroll
    for (int k = 0; k < 4; k++) {
        const float s1 = c1[k] + c1[k + 1] + c1[k + 2];
        const float s2 = c2[k] + c2[k + 1] + c2[k + 2];
        sta[k] = ct[k] + ct[k + 1] + ct[k + 2];
        s2a[k] = s2;
        mean[k] = s1 * inv9;
        ss[k] = fmaxf(fmaf(-s1, mean[k], s2), 0.0f);   // sum sq deviations
    }

    // ---- homogeneity abs-deviation sums (v dies after this) ----
    float sa[4];
#pragma unroll
    for (int k = 0; k < 4; k++) {
        float sA = 0.f, sB = 0.f, sC = 0.f;
#pragma unroll
        for (int j = 0; j < 3; j++) {
            sA += fabsf(v[0][k + j] - mean[k]);
            sB += fabsf(v[1][k + j] - mean[k]);
            sC += fabsf(v[2][k + j] - mean[k]);
        }
        sa[k] = sA + sB + sC;
    }

    const float E  = 0.60653065971263342f;   // exp(-0.5)
    const float EE = 1e-6f * E;
    float* __restrict__ o = out + (size_t)img * 4 * HW + h * 256 + wb;

    float4 f;
    // contrast
#pragma unroll
    for (int k = 0; k < 4; k++) {
        const float stdv = fsqrt_approx(ss[k] * 0.125f) + 1e-6f;  // ddof=1
        const float rs = frcp_approx(stdv);
        (&f.x)[k] = fmaf(ss[k] * inv9 * rs * rs, E, EE);
    }
    *(float4*)o = f;
    // energy
#pragma unroll
    for (int k = 0; k < 4; k++) (&f.x)[k] = fmaf(s2a[k] * inv9, E, EE);
    *(float4*)(o + HW) = f;
    // entropy
#pragma unroll
    for (int k = 0; k < 4; k++) (&f.x)[k] = fmaf(-sta[k] * inv9, E, EE);
    *(float4*)(o + 2 * HW) = f;
    // homogeneity
#pragma unroll
    for (int k = 0; k < 4; k++)
        (&f.x)[k] = fmaf(frcp_approx(fmaf(sa[k], inv9, 1.0f)), E, EE);
    *(float4*)(o + 3 * HW) = f;
}

extern "C" void kernel_launch(void* const* d_in, const int* in_sizes, int n_in,
                              void* d_out, int out_size)
{
    const float* x = (const float*)d_in[0];
    float* out = (float*)d_out;
    (void)in_sizes; (void)n_in; (void)out_size;

    dim3 block(32, 8);
    dim3 grid(2, 32, 8 * 16);
    glcm_martingale_kernel<<<grid, block>>>(x, out);
}

// round 8
// speedup vs baseline: 1.7138x; 1.0437x over previous
#include <cuda_runtime.h>

// x: [8,16,256,256] f32 -> out: [8,64,256,256] f32
// Each thread: 4 horizontal pixels. Own-aligned float4 loads only; halo column
// sums and halo values come from neighbor lanes via warp shuffle.
// Block 32x8 (warp = 128 contiguous cols of one row), grid (2,32,128).

#define HW 65536

__device__ __forceinline__ float fsqrt_approx(float a) {
    float r; asm("sqrt.approx.f32 %0, %1;" : "=f"(r) : "f"(a)); return r;
}
__device__ __forceinline__ float frcp_approx(float a) {
    float r; asm("rcp.approx.f32 %0, %1;" : "=f"(r) : "f"(a)); return r;
}
__device__ __forceinline__ float flg2_approx(float a) {
    float r; asm("lg2.approx.f32 %0, %1;" : "=f"(r) : "f"(a)); return r;
}

__global__ __launch_bounds__(256) void glcm_martingale_kernel(
    const float* __restrict__ x, float* __restrict__ out)
{
    const int img = blockIdx.z;                         // b*16+c
    const int h   = blockIdx.y * 8 + threadIdx.y;       // output row
    const int tx  = threadIdx.x;
    const int wb  = blockIdx.x * 128 + tx * 4;          // aligned col base
    const float* __restrict__ xin = x + (size_t)img * HW;

    // ---- own 4 columns, 3 rows (zero for OOB rows) ----
    float v[3][4];
#pragma unroll
    for (int r = 0; r < 3; r++) {
        const int gh = h - 1 + r;
        float4 a = make_float4(0.f, 0.f, 0.f, 0.f);
        if ((unsigned)gh < 256u)
            a = *(const float4*)(xin + gh * 256 + wb);
        v[r][0] = a.x; v[r][1] = a.y; v[r][2] = a.z; v[r][3] = a.w;
    }

    // ---- own column sums (lg2-based entropy term; ln2 folded into constant) ----
    float c1[4], c2[4], ct[4];
#pragma unroll
    for (int j = 0; j < 4; j++) {
        const float v0 = v[0][j], v1 = v[1][j], v2 = v[2][j];
        c1[j] = v0 + v1 + v2;
        c2[j] = fmaf(v0, v0, fmaf(v1, v1, v2 * v2));
        ct[j] = v0 * flg2_approx(v0 + 1e-6f)
              + v1 * flg2_approx(v1 + 1e-6f)
              + v2 * flg2_approx(v2 + 1e-6f);   // 0*lg2(eps) = 0 matches zero-pad
    }

    // ---- halo columns via warp shuffle (lanes 0/31 fixed up below) ----
    const unsigned FULL = 0xFFFFFFFFu;
    float vL[3], vR[3];
    vL[0] = __shfl_up_sync(FULL, v[0][3], 1);
    vL[1] = __shfl_up_sync(FULL, v[1][3], 1);
    vL[2] = __shfl_up_sync(FULL, v[2][3], 1);
    float c1L = __shfl_up_sync(FULL, c1[3], 1);
    float c2L = __shfl_up_sync(FULL, c2[3], 1);
    float ctL = __shfl_up_sync(FULL, ct[3], 1);
    vR[0] = __shfl_down_sync(FULL, v[0][0], 1);
    vR[1] = __shfl_down_sync(FULL, v[1][0], 1);
    vR[2] = __shfl_down_sync(FULL, v[2][0], 1);
    float c1R = __shfl_down_sync(FULL, c1[0], 1);
    float c2R = __shfl_down_sync(FULL, c2[0], 1);
    float ctR = __shfl_down_sync(FULL, ct[0], 1);

    if (tx == 0) {
        float a0 = 0.f, a1 = 0.f, a2 = 0.f;
        if (wb > 0) {   // left col wb-1 exists (bx==1)
            if ((unsigned)(h - 1) < 256u) a0 = xin[(h - 1) * 256 + wb - 1];
            a1 = xin[h * 256 + wb - 1];
            if ((unsigned)(h + 1) < 256u) a2 = xin[(h + 1) * 256 + wb - 1];
        }
        vL[0] = a0; vL[1] = a1; vL[2] = a2;
        c1L = a0 + a1 + a2;
        c2L = fmaf(a0, a0, fmaf(a1, a1, a2 * a2));
        ctL = a0 * flg2_approx(a0 + 1e-6f)
            + a1 * flg2_approx(a1 + 1e-6f)
            + a2 * flg2_approx(a2 + 1e-6f);
    }
    if (tx == 31) {
        float a0 = 0.f, a1 = 0.f, a2 = 0.f;
        if (wb + 4 < 256) {   // right col wb+4 exists (bx==0)
            if ((unsigned)(h - 1) < 256u) a0 = xin[(h - 1) * 256 + wb + 4];
            a1 = xin[h * 256 + wb + 4];
            if ((unsigned)(h + 1) < 256u) a2 = xin[(h + 1) * 256 + wb + 4];
        }
        vR[0] = a0; vR[1] = a1; vR[2] = a2;
        c1R = a0 + a1 + a2;
        c2R = fmaf(a0, a0, fmaf(a1, a1, a2 * a2));
        ctR = a0 * flg2_approx(a0 + 1e-6f)
            + a1 * flg2_approx(a1 + 1e-6f)
            + a2 * flg2_approx(a2 + 1e-6f);
    }

    // ---- assemble 6-wide arrays ----
    const float C1[6] = {c1L, c1[0], c1[1], c1[2], c1[3], c1R};
    const float C2[6] = {c2L, c2[0], c2[1], c2[2], c2[3], c2R};
    const float CT[6] = {ctL, ct[0], ct[1], ct[2], ct[3], ctR};
    const float VV0[6] = {vL[0], v[0][0], v[0][1], v[0][2], v[0][3], vR[0]};
    const float VV1[6] = {vL[1], v[1][0], v[1][1], v[1][2], v[1][3], vR[1]};
    const float VV2[6] = {vL[2], v[2][0], v[2][1], v[2][2], v[2][3], vR[2]};

    const float inv9 = 1.0f / 9.0f;
    const float E   = 0.60653065971263342f;            // exp(-0.5)
    const float EE  = 1e-6f * E;
    const float E9  = E / 9.0f;
    const float CEn = -0.6931471805599453f * E9;       // -ln2 * E/9 (entropy)

    float mean[4], ss[4], s2a[4], sta[4];
#pragma unroll
    for (int k = 0; k < 4; k++) {
        const float s1 = C1[k] + C1[k + 1] + C1[k + 2];
        const float s2 = C2[k] + C2[k + 1] + C2[k + 2];
        sta[k] = CT[k] + CT[k + 1] + CT[k + 2];
        s2a[k] = s2;
        mean[k] = s1 * inv9;
        ss[k] = fmaxf(fmaf(-s1, mean[k], s2), 0.0f);
    }

    float sa[4];
#pragma unroll
    for (int k = 0; k < 4; k++) {
        float sA = 0.f, sB = 0.f, sC = 0.f;
#pragma unroll
        for (int j = 0; j < 3; j++) {
            sA += fabsf(VV0[k + j] - mean[k]);
            sB += fabsf(VV1[k + j] - mean[k]);
            sC += fabsf(VV2[k + j] - mean[k]);
        }
        sa[k] = sA + sB + sC;
    }

    float* __restrict__ o = out + (size_t)img * 4 * HW + h * 256 + wb;
    float4 f;
    // contrast
#pragma unroll
    for (int k = 0; k < 4; k++) {
        const float stdv = fsqrt_approx(ss[k] * 0.125f) + 1e-6f;  // ddof=1
        const float rs = frcp_approx(stdv);
        (&f.x)[k] = fmaf(ss[k] * E9, rs * rs, EE);
    }
    *(float4*)o = f;
    // energy
#pragma unroll
    for (int k = 0; k < 4; k++) (&f.x)[k] = fmaf(s2a[k], E9, EE);
    *(float4*)(o + HW) = f;
    // entropy
#pragma unroll
    for (int k = 0; k < 4; k++) (&f.x)[k] = fmaf(sta[k], CEn, EE);
    *(float4*)(o + 2 * HW) = f;
    // homogeneity
#pragma unroll
    for (int k = 0; k < 4; k++)
        (&f.x)[k] = fmaf(frcp_approx(fmaf(sa[k], inv9, 1.0f)), E, EE);
    *(float4*)(o + 3 * HW) = f;
}

extern "C" void kernel_launch(void* const* d_in, const int* in_sizes, int n_in,
                              void* d_out, int out_size)
{
    const float* x = (const float*)d_in[0];
    float* out = (float*)d_out;
    (void)in_sizes; (void)n_in; (void)out_size;

    dim3 block(32, 8);
    dim3 grid(2, 32, 8 * 16);
    glcm_martingale_kernel<<<grid, block>>>(x, out);
}